// round 2
// baseline (speedup 1.0000x reference)
#include <cuda_runtime.h>
#include <math.h>

#define Bz 4
#define Nn 4096
#define Cin 128
#define Cout 128
#define Kk 10
#define Ll 50
#define Ne 65536

// ---------------- scratch (static device globals; no allocs) ----------------
__device__ __align__(16) float  g_filt[2 * Bz * Nn * Cout];  // 16 MB: fea@W1, fea@W2
__device__ __align__(16) float  g_y[Bz * Nn * Cout];         // 8 MB: phi_inv spmm output
__device__ __align__(16) float  g_res[Bz * Nn * Cout];       // 8 MB: summed conv output
__device__ __align__(16) float4 g_h[2][Nn];                  // ping-pong hidden, batch-packed [n][b]
__device__ __align__(16) float  g_gih[Ll * Bz * Nn];         // precomputed x@W_ih.T + b_ih + b_hh

// ---------------- helpers ----------------
__device__ __forceinline__ float gelu_exact(float x) {
    return 0.5f * x * (1.0f + erff(x * 0.7071067811865476f));
}

// ---------------- zero kernels ----------------
__global__ void k_zero_all() {
    int i = blockIdx.x * blockDim.x + threadIdx.x;   // 524288 threads
    float4 z = make_float4(0.f, 0.f, 0.f, 0.f);
    ((float4*)g_res)[i] = z;
    ((float4*)g_y)[i] = z;
    if (i < 2 * Nn) ((float4*)g_h)[i] = z;
}

__global__ void k_zero_y() {
    int i = blockIdx.x * blockDim.x + threadIdx.x;
    ((float4*)g_y)[i] = make_float4(0.f, 0.f, 0.f, 0.f);
}

// ---------------- filt = fea @ W_l  (both layers, blockIdx.y selects W) ----------------
__global__ void k_gemm_filt(const float* __restrict__ fea,
                            const float* __restrict__ W1,
                            const float* __restrict__ W2) {
    extern __shared__ float4 Ws[];  // 128x128 f32 = 64 KB
    const float4* W = (const float4*)(blockIdx.y ? W2 : W1);
    for (int i = threadIdx.x; i < Cin * Cout / 4; i += blockDim.x) Ws[i] = W[i];
    __syncthreads();

    int warp = threadIdx.x >> 5, lane = threadIdx.x & 31;
    int nw = blockDim.x >> 5;
    float* out = g_filt + (size_t)blockIdx.y * Bz * Nn * Cout;
    for (int row = blockIdx.x * nw + warp; row < Bz * Nn; row += gridDim.x * nw) {
        const float* fr = fea + (size_t)row * Cin;
        float4 acc = make_float4(0.f, 0.f, 0.f, 0.f);
#pragma unroll 8
        for (int c = 0; c < Cin; c++) {
            float f = __ldg(fr + c);            // warp-broadcast load
            float4 w = Ws[c * (Cout / 4) + lane];
            acc.x = fmaf(f, w.x, acc.x);
            acc.y = fmaf(f, w.y, acc.y);
            acc.z = fmaf(f, w.z, acc.z);
            acc.w = fmaf(f, w.w, acc.w);
        }
        ((float4*)(out + (size_t)row * Cout))[lane] = acc;
    }
}

// ---------------- COO spmm: Y[b,r,:] += v (* d[c]) * X[b,c,:]  (warp per edge) ----------------
__global__ void k_spmm(const int* __restrict__ idx, const float* __restrict__ val,
                       const float* __restrict__ dvec, int xsel, int to_res) {
    int g = blockIdx.x * blockDim.x + threadIdx.x;
    int w = g >> 5, lane = g & 31;
    if (w >= Bz * Ne) return;
    int b = w >> 16;            // Ne == 65536
    int e = w & (Ne - 1);
    const int* ib = idx + (size_t)b * 2 * Ne;
    int r = ib[e];
    int c = ib[Ne + e];
    float v = val[(size_t)b * Ne + e];
    if (dvec) v *= __ldg(dvec + c);
    const float* X = (xsel == 2) ? g_y : (g_filt + (size_t)xsel * Bz * Nn * Cout);
    float* Y = to_res ? g_res : g_y;
    float4 xv = ((const float4*)(X + ((size_t)b * Nn + c) * Cout))[lane];
    float4 add = make_float4(v * xv.x, v * xv.y, v * xv.z, v * xv.w);
    atomicAdd(((float4*)(Y + ((size_t)b * Nn + r) * Cout)) + lane, add);
}

// ---------------- gih[t,b,i] = b_ih[i] + b_hh[i] + item_emb[joblst[b,t]] . W_ih[i,:] ----------------
__global__ void k_gih(const int* __restrict__ joblst,
                      const float* __restrict__ item_emb,
                      const float* __restrict__ W_ih,
                      const float* __restrict__ b_ih,
                      const float* __restrict__ b_hh) {
    int i = blockIdx.x * blockDim.x + threadIdx.x;
    int tb = blockIdx.y;
    int t = tb / Bz;
    int b = tb - t * Bz;
    int j = joblst[(size_t)b * Ll + t];   // int32: JAX x64-disabled downgrades int64
    const float4* emb4 = (const float4*)(item_emb + (size_t)j * Cout);
    const float4* w4 = (const float4*)(W_ih + (size_t)i * Cout);
    float acc = b_ih[i] + b_hh[i];
#pragma unroll
    for (int c = 0; c < Cout / 4; c++) {
        float4 e = __ldg(emb4 + c);
        float4 w = __ldg(w4 + c);
        acc = fmaf(e.x, w.x, acc);
        acc = fmaf(e.y, w.y, acc);
        acc = fmaf(e.z, w.z, acc);
        acc = fmaf(e.w, w.w, acc);
    }
    g_gih[((size_t)t * Bz + b) * Nn + i] = acc;
}

// ---------------- one RNN step: hout[n] = tanh(gih_t + W_hh[n,:] . hin) ----------------
// block = 256 threads (8 warps), 2 rows per warp, grid = 256 blocks, h cached in 64KB smem
__global__ void k_rnn_step(const float* __restrict__ Whh, int t) {
    extern __shared__ float4 hs[];  // Nn float4 = 64 KB, batch-packed
    const float4* hin = g_h[t & 1];
    float4* hout = g_h[(t + 1) & 1];
    const float* gt = g_gih + (size_t)t * Bz * Nn;
    for (int i = threadIdx.x; i < Nn; i += blockDim.x) hs[i] = hin[i];
    __syncthreads();

    int warp = threadIdx.x >> 5, lane = threadIdx.x & 31;
#pragma unroll
    for (int rr = 0; rr < 2; rr++) {
        int i = blockIdx.x * 16 + warp * 2 + rr;
        const float* wr = Whh + (size_t)i * Nn;
        float a0 = 0.f, a1 = 0.f, a2 = 0.f, a3 = 0.f;
#pragma unroll 8
        for (int j = lane; j < Nn; j += 32) {
            float w = __ldg(wr + j);
            float4 h = hs[j];
            a0 = fmaf(w, h.x, a0);
            a1 = fmaf(w, h.y, a1);
            a2 = fmaf(w, h.z, a2);
            a3 = fmaf(w, h.w, a3);
        }
#pragma unroll
        for (int off = 16; off; off >>= 1) {
            a0 += __shfl_down_sync(0xffffffffu, a0, off);
            a1 += __shfl_down_sync(0xffffffffu, a1, off);
            a2 += __shfl_down_sync(0xffffffffu, a2, off);
            a3 += __shfl_down_sync(0xffffffffu, a3, off);
        }
        if (lane == 0) {
            hout[i] = make_float4(tanhf(a0 + gt[0 * Nn + i]),
                                  tanhf(a1 + gt[1 * Nn + i]),
                                  tanhf(a2 + gt[2 * Nn + i]),
                                  tanhf(a3 + gt[3 * Nn + i]));
        }
    }
}

// ---------------- epilogue: out[b,n,k] = sigmoid(gelu(res.dW_k + db_k) * gelu(h_final[b,n])) ----------------
__global__ void k_epi(const float* __restrict__ dW, const float* __restrict__ db,
                      float* __restrict__ out) {
    __shared__ float dWs[Kk * Cout];
    __shared__ float dbs[Kk];
    for (int i = threadIdx.x; i < Kk * Cout; i += blockDim.x) dWs[i] = dW[i];
    if (threadIdx.x < Kk) dbs[threadIdx.x] = db[threadIdx.x];
    __syncthreads();

    int warp = threadIdx.x >> 5, lane = threadIdx.x & 31;
    int gw = blockIdx.x * (blockDim.x >> 5) + warp;  // = b*Nn + n
    if (gw >= Bz * Nn) return;
    int b = gw >> 12;           // Nn == 4096
    int n = gw & (Nn - 1);

    float4 r = ((const float4*)(g_res + (size_t)gw * Cout))[lane];
    // final hidden lives in g_h[0] (Ll even); layout [n][b]
    float hb = ((const float*)g_h)[(size_t)n * 4 + b];
    float eh = gelu_exact(hb);

#pragma unroll
    for (int k = 0; k < Kk; k++) {
        const float4* w4 = (const float4*)(dWs + k * Cout);
        float4 w = w4[lane];
        float p = r.x * w.x + r.y * w.y + r.z * w.z + r.w * w.w;
#pragma unroll
        for (int off = 16; off; off >>= 1) p += __shfl_xor_sync(0xffffffffu, p, off);
        if (lane == 0) {
            float s = gelu_exact(p + dbs[k]);
            float v = s * eh;
            out[(size_t)gw * Kk + k] = 1.0f / (1.0f + expf(-v));
        }
    }
}

// ---------------- launch ----------------
extern "C" void kernel_launch(void* const* d_in, const int* in_sizes, int n_in,
                              void* d_out, int out_size) {
    const int*   phi1_idx     = (const int*)d_in[0];
    const float* phi1_val     = (const float*)d_in[1];
    const int*   phi1_inv_idx = (const int*)d_in[2];
    const float* phi1_inv_val = (const float*)d_in[3];
    const int*   phi2_idx     = (const int*)d_in[4];
    const float* phi2_val     = (const float*)d_in[5];
    const int*   phi2_inv_idx = (const int*)d_in[6];
    const float* phi2_inv_val = (const float*)d_in[7];
    const float* fea          = (const float*)d_in[8];
    const int*   joblst       = (const int*)d_in[9];
    const float* W1           = (const float*)d_in[10];
    const float* d1           = (const float*)d_in[11];
    const float* W2           = (const float*)d_in[12];
    const float* d2           = (const float*)d_in[13];
    const float* W_ih         = (const float*)d_in[14];
    const float* W_hh         = (const float*)d_in[15];
    const float* b_ih         = (const float*)d_in[16];
    const float* b_hh         = (const float*)d_in[17];
    const float* dense_W      = (const float*)d_in[18];
    const float* dense_b      = (const float*)d_in[19];
    const float* item_emb     = (const float*)d_in[20];
    float*       out          = (float*)d_out;

    cudaFuncSetAttribute(k_gemm_filt, cudaFuncAttributeMaxDynamicSharedMemorySize, 65536);
    cudaFuncSetAttribute(k_rnn_step, cudaFuncAttributeMaxDynamicSharedMemorySize, 65536);

    // init scratch
    k_zero_all<<<2048, 256>>>();

    // dense inputs
    k_gemm_filt<<<dim3(256, 2), 256, 65536>>>(fea, W1, W2);
    k_gih<<<dim3(Nn / 256, Ll * Bz), 256>>>(joblst, item_emb, W_ih, b_ih, b_hh);

    // layer 1: y = phi1_inv @ filt0 ; res += phi1 @ (d1 * y)
    k_spmm<<<32768, 256>>>(phi1_inv_idx, phi1_inv_val, nullptr, 0, 0);
    k_spmm<<<32768, 256>>>(phi1_idx, phi1_val, d1, 2, 1);

    // layer 2: y = phi2_inv @ filt1 ; res += phi2 @ (d2 * y)
    k_zero_y<<<2048, 256>>>();
    k_spmm<<<32768, 256>>>(phi2_inv_idx, phi2_inv_val, nullptr, 1, 0);
    k_spmm<<<32768, 256>>>(phi2_idx, phi2_val, d2, 2, 1);

    // RNN: 50 sequential steps
    for (int t = 0; t < Ll; t++) k_rnn_step<<<256, 256, 65536>>>(W_hh, t);

    // epilogue
    k_epi<<<(Bz * Nn) / 8, 256>>>(dense_W, dense_b, out);
}

// round 3
// speedup vs baseline: 1.1252x; 1.1252x over previous
#include <cuda_runtime.h>
#include <cuda_fp16.h>
#include <math.h>

#define Bz 4
#define Nn 4096
#define Cin 128
#define Cout 128
#define Kk 10
#define Ll 50
#define Ne 65536

// ---------------- scratch (static device globals; no allocs) ----------------
__device__ __align__(16) float  g_filt[2 * Bz * Nn * Cout];  // 16 MB
__device__ __align__(16) float  g_y[Bz * Nn * Cout];         // 8 MB
__device__ __align__(16) float  g_res[Bz * Nn * Cout];       // 8 MB
__device__ __align__(16) float4 g_h[2][Nn];                  // ping-pong hidden, [n][b]
__device__ __align__(16) float  g_gih[Ll * Bz * Nn];         // x@W_ih.T + b_ih + b_hh
__device__ __align__(16) __half g_whh[Nn * Nn];              // 32 MB fp16 copy of W_hh

// ---------------- helpers ----------------
__device__ __forceinline__ float gelu_exact(float x) {
    return 0.5f * x * (1.0f + erff(x * 0.7071067811865476f));
}

__device__ __forceinline__ float2 ffma2(float2 a, float2 b, float2 c) {
    unsigned long long au = *reinterpret_cast<unsigned long long*>(&a);
    unsigned long long bu = *reinterpret_cast<unsigned long long*>(&b);
    unsigned long long cu = *reinterpret_cast<unsigned long long*>(&c);
    unsigned long long du;
    asm("fma.rn.f32x2 %0, %1, %2, %3;" : "=l"(du) : "l"(au), "l"(bu), "l"(cu));
    return *reinterpret_cast<float2*>(&du);
}

// ---------------- zero kernels ----------------
__global__ void k_zero_all() {
    int i = blockIdx.x * blockDim.x + threadIdx.x;   // 524288 threads
    float4 z = make_float4(0.f, 0.f, 0.f, 0.f);
    ((float4*)g_res)[i] = z;
    ((float4*)g_y)[i] = z;
    if (i < 2 * Nn) ((float4*)g_h)[i] = z;
}

__global__ void k_zero_y() {
    int i = blockIdx.x * blockDim.x + threadIdx.x;
    ((float4*)g_y)[i] = make_float4(0.f, 0.f, 0.f, 0.f);
}

// ---------------- W_hh fp32 -> fp16 (4 elements / thread) ----------------
__global__ void k_cvt_whh(const float* __restrict__ W) {
    int i = blockIdx.x * blockDim.x + threadIdx.x;   // Nn*Nn/4 threads
    float4 w = ((const float4*)W)[i];
    __half2* o = (__half2*)(g_whh + (size_t)i * 4);
    o[0] = __floats2half2_rn(w.x, w.y);
    o[1] = __floats2half2_rn(w.z, w.w);
}

// ---------------- filt = fea @ W_l ----------------
__global__ void k_gemm_filt(const float* __restrict__ fea,
                            const float* __restrict__ W1,
                            const float* __restrict__ W2) {
    extern __shared__ float4 Ws[];  // 64 KB
    const float4* W = (const float4*)(blockIdx.y ? W2 : W1);
    for (int i = threadIdx.x; i < Cin * Cout / 4; i += blockDim.x) Ws[i] = W[i];
    __syncthreads();

    int warp = threadIdx.x >> 5, lane = threadIdx.x & 31;
    int nw = blockDim.x >> 5;
    float* out = g_filt + (size_t)blockIdx.y * Bz * Nn * Cout;
    for (int row = blockIdx.x * nw + warp; row < Bz * Nn; row += gridDim.x * nw) {
        const float* fr = fea + (size_t)row * Cin;
        float4 acc = make_float4(0.f, 0.f, 0.f, 0.f);
#pragma unroll 8
        for (int c = 0; c < Cin; c++) {
            float f = __ldg(fr + c);
            float4 w = Ws[c * (Cout / 4) + lane];
            acc.x = fmaf(f, w.x, acc.x);
            acc.y = fmaf(f, w.y, acc.y);
            acc.z = fmaf(f, w.z, acc.z);
            acc.w = fmaf(f, w.w, acc.w);
        }
        ((float4*)(out + (size_t)row * Cout))[lane] = acc;
    }
}

// ---------------- COO spmm (warp per edge, vector atomics) ----------------
__global__ void k_spmm(const int* __restrict__ idx, const float* __restrict__ val,
                       const float* __restrict__ dvec, int xsel, int to_res) {
    int g = blockIdx.x * blockDim.x + threadIdx.x;
    int w = g >> 5, lane = g & 31;
    if (w >= Bz * Ne) return;
    int b = w >> 16;
    int e = w & (Ne - 1);
    const int* ib = idx + (size_t)b * 2 * Ne;
    int r = ib[e];
    int c = ib[Ne + e];
    float v = val[(size_t)b * Ne + e];
    if (dvec) v *= __ldg(dvec + c);
    const float* X = (xsel == 2) ? g_y : (g_filt + (size_t)xsel * Bz * Nn * Cout);
    float* Y = to_res ? g_res : g_y;
    float4 xv = ((const float4*)(X + ((size_t)b * Nn + c) * Cout))[lane];
    float4 add = make_float4(v * xv.x, v * xv.y, v * xv.z, v * xv.w);
    atomicAdd(((float4*)(Y + ((size_t)b * Nn + r) * Cout)) + lane, add);
}

// ---------------- gih precompute ----------------
__global__ void k_gih(const int* __restrict__ joblst,
                      const float* __restrict__ item_emb,
                      const float* __restrict__ W_ih,
                      const float* __restrict__ b_ih,
                      const float* __restrict__ b_hh) {
    int i = blockIdx.x * blockDim.x + threadIdx.x;
    int tb = blockIdx.y;
    int t = tb / Bz;
    int b = tb - t * Bz;
    int j = joblst[(size_t)b * Ll + t];
    const float4* emb4 = (const float4*)(item_emb + (size_t)j * Cout);
    const float4* w4 = (const float4*)(W_ih + (size_t)i * Cout);
    float acc = b_ih[i] + b_hh[i];
#pragma unroll
    for (int c = 0; c < Cout / 4; c++) {
        float4 e = __ldg(emb4 + c);
        float4 w = __ldg(w4 + c);
        acc = fmaf(e.x, w.x, acc);
        acc = fmaf(e.y, w.y, acc);
        acc = fmaf(e.z, w.z, acc);
        acc = fmaf(e.w, w.w, acc);
    }
    g_gih[((size_t)t * Bz + b) * Nn + i] = acc;
}

// ---------------- RNN step: fp16 weights, 4 rows/warp, f32x2 FMA ----------------
// grid = 128 blocks x 256 threads (8 warps); 128*8 = 1024 warps * 4 rows = 4096
__global__ void k_rnn_step(int t) {
    extern __shared__ float4 hs[];  // 4096 float4 = 64 KB, XOR-swizzled
    const float4* hin = g_h[t & 1];
    float4* hout = g_h[(t + 1) & 1];
    const float* gt = g_gih + (size_t)t * Bz * Nn;

    // copy h into swizzled smem
    for (int j = threadIdx.x; j < Nn; j += blockDim.x)
        hs[j ^ ((j >> 3) & 7)] = hin[j];
    __syncthreads();

    int warp = threadIdx.x >> 5, lane = threadIdx.x & 31;
    int gw = blockIdx.x * 8 + warp;        // 0..1023
    int row0 = gw * 4;
    int sw = lane & 7;

    const uint4* w0 = (const uint4*)(g_whh + (size_t)(row0 + 0) * Nn);
    const uint4* w1 = (const uint4*)(g_whh + (size_t)(row0 + 1) * Nn);
    const uint4* w2 = (const uint4*)(g_whh + (size_t)(row0 + 2) * Nn);
    const uint4* w3 = (const uint4*)(g_whh + (size_t)(row0 + 3) * Nn);

    float2 acc[4][4];
#pragma unroll
    for (int r = 0; r < 4; r++)
#pragma unroll
        for (int b = 0; b < 4; b++) acc[r][b] = make_float2(0.f, 0.f);

    for (int c = 0; c < 16; c++) {
        int off = c * 32 + lane;           // uint4 index within row (8 halves)
        uint4 wv[4];
        wv[0] = __ldg(w0 + off);
        wv[1] = __ldg(w1 + off);
        wv[2] = __ldg(w2 + off);
        wv[3] = __ldg(w3 + off);

        int base = c * 256 + lane * 8;     // logical float4 (=j) index
        float4 hv[8];
#pragma unroll
        for (int k = 0; k < 8; k++)
            hv[k] = hs[base + (k ^ sw)];   // hv[k^sw] holds logical j=base+(k^sw)... see below
        // note: hs physical index p = j ^ sw, so hs[base + (k^sw)] is logical j = base + k? No:
        // phys(j) = j ^ ((j>>3)&7) = base + ((j&7) ^ sw). For logical j = base + k, phys = base + (k ^ sw).
        // so hv[k] above, loaded from hs[base + (k^sw)], IS logical j = base + k.  (correct)

#pragma unroll
        for (int k = 0; k < 8; k += 2) {
            // h operand pairs across j=(base+k, base+k+1), per batch
            float2 hp0 = make_float2(hv[k].x, hv[k + 1].x);
            float2 hp1 = make_float2(hv[k].y, hv[k + 1].y);
            float2 hp2 = make_float2(hv[k].z, hv[k + 1].z);
            float2 hp3 = make_float2(hv[k].w, hv[k + 1].w);
#pragma unroll
            for (int r = 0; r < 4; r++) {
                __half2 wh = ((const __half2*)&wv[r])[k >> 1];
                float2 wf = __half22float2(wh);
                acc[r][0] = ffma2(wf, hp0, acc[r][0]);
                acc[r][1] = ffma2(wf, hp1, acc[r][1]);
                acc[r][2] = ffma2(wf, hp2, acc[r][2]);
                acc[r][3] = ffma2(wf, hp3, acc[r][3]);
            }
        }
    }

    // reduce and write
#pragma unroll
    for (int r = 0; r < 4; r++) {
        float s0 = acc[r][0].x + acc[r][0].y;
        float s1 = acc[r][1].x + acc[r][1].y;
        float s2 = acc[r][2].x + acc[r][2].y;
        float s3 = acc[r][3].x + acc[r][3].y;
#pragma unroll
        for (int o = 16; o; o >>= 1) {
            s0 += __shfl_down_sync(0xffffffffu, s0, o);
            s1 += __shfl_down_sync(0xffffffffu, s1, o);
            s2 += __shfl_down_sync(0xffffffffu, s2, o);
            s3 += __shfl_down_sync(0xffffffffu, s3, o);
        }
        if (lane == 0) {
            int i = row0 + r;
            hout[i] = make_float4(tanhf(s0 + gt[0 * Nn + i]),
                                  tanhf(s1 + gt[1 * Nn + i]),
                                  tanhf(s2 + gt[2 * Nn + i]),
                                  tanhf(s3 + gt[3 * Nn + i]));
        }
    }
}

// ---------------- epilogue ----------------
__global__ void k_epi(const float* __restrict__ dW, const float* __restrict__ db,
                      float* __restrict__ out) {
    __shared__ float dWs[Kk * Cout];
    __shared__ float dbs[Kk];
    for (int i = threadIdx.x; i < Kk * Cout; i += blockDim.x) dWs[i] = dW[i];
    if (threadIdx.x < Kk) dbs[threadIdx.x] = db[threadIdx.x];
    __syncthreads();

    int warp = threadIdx.x >> 5, lane = threadIdx.x & 31;
    int gw = blockIdx.x * (blockDim.x >> 5) + warp;  // = b*Nn + n
    if (gw >= Bz * Nn) return;
    int b = gw >> 12;
    int n = gw & (Nn - 1);

    float4 r = ((const float4*)(g_res + (size_t)gw * Cout))[lane];
    float hb = ((const float*)g_h)[(size_t)n * 4 + b];   // g_h[0], [n][b]
    float eh = gelu_exact(hb);

#pragma unroll
    for (int k = 0; k < Kk; k++) {
        const float4* w4 = (const float4*)(dWs + k * Cout);
        float4 w = w4[lane];
        float p = r.x * w.x + r.y * w.y + r.z * w.z + r.w * w.w;
#pragma unroll
        for (int off = 16; off; off >>= 1) p += __shfl_xor_sync(0xffffffffu, p, off);
        if (lane == 0) {
            float s = gelu_exact(p + dbs[k]);
            float v = s * eh;
            out[(size_t)gw * Kk + k] = 1.0f / (1.0f + expf(-v));
        }
    }
}

// ---------------- launch ----------------
extern "C" void kernel_launch(void* const* d_in, const int* in_sizes, int n_in,
                              void* d_out, int out_size) {
    const int*   phi1_idx     = (const int*)d_in[0];
    const float* phi1_val     = (const float*)d_in[1];
    const int*   phi1_inv_idx = (const int*)d_in[2];
    const float* phi1_inv_val = (const float*)d_in[3];
    const int*   phi2_idx     = (const int*)d_in[4];
    const float* phi2_val     = (const float*)d_in[5];
    const int*   phi2_inv_idx = (const int*)d_in[6];
    const float* phi2_inv_val = (const float*)d_in[7];
    const float* fea          = (const float*)d_in[8];
    const int*   joblst       = (const int*)d_in[9];
    const float* W1           = (const float*)d_in[10];
    const float* d1           = (const float*)d_in[11];
    const float* W2           = (const float*)d_in[12];
    const float* d2           = (const float*)d_in[13];
    const float* W_ih         = (const float*)d_in[14];
    const float* W_hh         = (const float*)d_in[15];
    const float* b_ih         = (const float*)d_in[16];
    const float* b_hh         = (const float*)d_in[17];
    const float* dense_W      = (const float*)d_in[18];
    const float* dense_b      = (const float*)d_in[19];
    const float* item_emb     = (const float*)d_in[20];
    float*       out          = (float*)d_out;

    cudaFuncSetAttribute(k_gemm_filt, cudaFuncAttributeMaxDynamicSharedMemorySize, 65536);
    cudaFuncSetAttribute(k_rnn_step, cudaFuncAttributeMaxDynamicSharedMemorySize, 65536);

    // init scratch + fp16 weight conversion
    k_zero_all<<<2048, 256>>>();
    k_cvt_whh<<<(Nn * Nn / 4) / 256, 256>>>(W_hh);

    // dense inputs
    k_gemm_filt<<<dim3(256, 2), 256, 65536>>>(fea, W1, W2);
    k_gih<<<dim3(Nn / 256, Ll * Bz), 256>>>(joblst, item_emb, W_ih, b_ih, b_hh);

    // layer 1
    k_spmm<<<32768, 256>>>(phi1_inv_idx, phi1_inv_val, nullptr, 0, 0);
    k_spmm<<<32768, 256>>>(phi1_idx, phi1_val, d1, 2, 1);

    // layer 2
    k_zero_y<<<2048, 256>>>();
    k_spmm<<<32768, 256>>>(phi2_inv_idx, phi2_inv_val, nullptr, 1, 0);
    k_spmm<<<32768, 256>>>(phi2_idx, phi2_val, d2, 2, 1);

    // RNN: 50 sequential steps
    for (int t = 0; t < Ll; t++) k_rnn_step<<<128, 256, 65536>>>(t);

    // epilogue
    k_epi<<<(Bz * Nn) / 8, 256>>>(dense_W, dense_b, out);
}

// round 4
// speedup vs baseline: 1.3252x; 1.1778x over previous
#include <cuda_runtime.h>
#include <cuda_fp16.h>
#include <math.h>

#define Bz 4
#define Nn 4096
#define Cin 128
#define Cout 128
#define Kk 10
#define Ll 50
#define Ne 65536
#define TBtot (Ll * Bz)   // 200

// ---------------- scratch (static device globals; no allocs) ----------------
__device__ __align__(16) float  g_filt[2 * Bz * Nn * Cout];  // 16 MB
__device__ __align__(16) float  g_y[Bz * Nn * Cout];         // 8 MB
__device__ __align__(16) float  g_res[Bz * Nn * Cout];       // 8 MB
__device__ __align__(16) float4 g_h[2][Nn];                  // ping-pong hidden, [n][b]
__device__ __align__(16) float  g_gih[TBtot * Nn];           // [t][b][i]
__device__ __align__(16) __half g_whh[Nn * Nn];              // 32 MB fp16 W_hh

// ---------------- helpers ----------------
__device__ __forceinline__ float gelu_exact(float x) {
    return 0.5f * x * (1.0f + erff(x * 0.7071067811865476f));
}

__device__ __forceinline__ float2 ffma2(float2 a, float2 b, float2 c) {
    unsigned long long au = *reinterpret_cast<unsigned long long*>(&a);
    unsigned long long bu = *reinterpret_cast<unsigned long long*>(&b);
    unsigned long long cu = *reinterpret_cast<unsigned long long*>(&c);
    unsigned long long du;
    asm("fma.rn.f32x2 %0, %1, %2, %3;" : "=l"(du) : "l"(au), "l"(bu), "l"(cu));
    return *reinterpret_cast<float2*>(&du);
}

// ---------------- zero kernels ----------------
__global__ void k_zero_all() {
    int i = blockIdx.x * blockDim.x + threadIdx.x;   // 524288 threads
    float4 z = make_float4(0.f, 0.f, 0.f, 0.f);
    ((float4*)g_res)[i] = z;
    ((float4*)g_y)[i] = z;
    if (i < 2 * Nn) ((float4*)g_h)[i] = z;
}

__global__ void k_zero_y() {
    int i = blockIdx.x * blockDim.x + threadIdx.x;
    ((float4*)g_y)[i] = make_float4(0.f, 0.f, 0.f, 0.f);
}

// ---------------- W_hh fp32 -> fp16 ----------------
__global__ void k_cvt_whh(const float* __restrict__ W) {
    int i = blockIdx.x * blockDim.x + threadIdx.x;   // Nn*Nn/4 threads
    float4 w = ((const float4*)W)[i];
    __half2* o = (__half2*)(g_whh + (size_t)i * 4);
    o[0] = __floats2half2_rn(w.x, w.y);
    o[1] = __floats2half2_rn(w.z, w.w);
}

// ---------------- filt = fea @ W_l ----------------
__global__ void k_gemm_filt(const float* __restrict__ fea,
                            const float* __restrict__ W1,
                            const float* __restrict__ W2) {
    extern __shared__ float4 Ws[];  // 64 KB
    const float4* W = (const float4*)(blockIdx.y ? W2 : W1);
    for (int i = threadIdx.x; i < Cin * Cout / 4; i += blockDim.x) Ws[i] = W[i];
    __syncthreads();

    int warp = threadIdx.x >> 5, lane = threadIdx.x & 31;
    int nw = blockDim.x >> 5;
    float* out = g_filt + (size_t)blockIdx.y * Bz * Nn * Cout;
    for (int row = blockIdx.x * nw + warp; row < Bz * Nn; row += gridDim.x * nw) {
        const float* fr = fea + (size_t)row * Cin;
        float4 acc = make_float4(0.f, 0.f, 0.f, 0.f);
#pragma unroll 8
        for (int c = 0; c < Cin; c++) {
            float f = __ldg(fr + c);
            float4 w = Ws[c * (Cout / 4) + lane];
            acc.x = fmaf(f, w.x, acc.x);
            acc.y = fmaf(f, w.y, acc.y);
            acc.z = fmaf(f, w.z, acc.z);
            acc.w = fmaf(f, w.w, acc.w);
        }
        ((float4*)(out + (size_t)row * Cout))[lane] = acc;
    }
}

// ---------------- COO spmm (warp per edge, vector atomics) ----------------
__global__ void k_spmm(const int* __restrict__ idx, const float* __restrict__ val,
                       const float* __restrict__ dvec, int xsel, int to_res) {
    int g = blockIdx.x * blockDim.x + threadIdx.x;
    int w = g >> 5, lane = g & 31;
    if (w >= Bz * Ne) return;
    int b = w >> 16;
    int e = w & (Ne - 1);
    const int* ib = idx + (size_t)b * 2 * Ne;
    int r = ib[e];
    int c = ib[Ne + e];
    float v = val[(size_t)b * Ne + e];
    if (dvec) v *= __ldg(dvec + c);
    const float* X = (xsel == 2) ? g_y : (g_filt + (size_t)xsel * Bz * Nn * Cout);
    float* Y = to_res ? g_res : g_y;
    float4 xv = ((const float4*)(X + ((size_t)b * Nn + c) * Cout))[lane];
    float4 add = make_float4(v * xv.x, v * xv.y, v * xv.z, v * xv.w);
    atomicAdd(((float4*)(Y + ((size_t)b * Nn + r) * Cout)) + lane, add);
}

// ---------------- gih: tiled GEMM  C[200,4096] = E[200,128] @ W_ih^T ----------------
// grid (32, 2): 128 i's x 128 tb's per block. smem: As[c][i], Es[c][tb], 132-float rows.
__global__ void k_gih(const int* __restrict__ joblst,
                      const float* __restrict__ item_emb,
                      const float* __restrict__ W_ih,
                      const float* __restrict__ b_ih,
                      const float* __restrict__ b_hh) {
    extern __shared__ float sm[];
    float* As = sm;                   // [128][132]
    float* Es = sm + 128 * 132;       // [128][132]
    int tid = threadIdx.x, lane = tid & 31, warp = tid >> 5;
    int i0 = blockIdx.x * 128, tb0 = blockIdx.y * 128;

    // W tile transposed: As[c][il] = W_ih[i0+il][c]
#pragma unroll 4
    for (int r = 0; r < 16; r++) {
        int il = warp * 16 + r;
        float4 w = __ldg((const float4*)(W_ih + (size_t)(i0 + il) * Cin) + lane);
        As[(4 * lane + 0) * 132 + il] = w.x;
        As[(4 * lane + 1) * 132 + il] = w.y;
        As[(4 * lane + 2) * 132 + il] = w.z;
        As[(4 * lane + 3) * 132 + il] = w.w;
    }
    // emb tile transposed: Es[c][tbl] = item_emb[joblst[tb]][c]
#pragma unroll 4
    for (int r = 0; r < 16; r++) {
        int tbl = warp * 16 + r;
        int tb = tb0 + tbl;
        int j = 0;
        if (tb < TBtot) { int t = tb >> 2, b = tb & 3; j = joblst[b * Ll + t]; }
        float4 e = __ldg((const float4*)(item_emb + (size_t)j * Cout) + lane);
        Es[(4 * lane + 0) * 132 + tbl] = e.x;
        Es[(4 * lane + 1) * 132 + tbl] = e.y;
        Es[(4 * lane + 2) * 132 + tbl] = e.z;
        Es[(4 * lane + 3) * 132 + tbl] = e.w;
    }
    __syncthreads();

    int ti = lane * 4;       // 4 i's per thread
    int tt = warp * 16;      // 16 tb's per thread (warp-uniform)
    float2 acc[4][8];
#pragma unroll
    for (int ii = 0; ii < 4; ii++)
#pragma unroll
        for (int p = 0; p < 8; p++) acc[ii][p] = make_float2(0.f, 0.f);

    for (int c = 0; c < 128; c++) {
        float4 a = ((const float4*)(As + c * 132))[lane];          // conflict-free
        const float4* er = (const float4*)(Es + c * 132) + (tt >> 2);  // broadcast
        float4 e0 = er[0], e1 = er[1], e2 = er[2], e3 = er[3];
        float2 ep[8] = { {e0.x, e0.y}, {e0.z, e0.w}, {e1.x, e1.y}, {e1.z, e1.w},
                         {e2.x, e2.y}, {e2.z, e2.w}, {e3.x, e3.y}, {e3.z, e3.w} };
        float av[4] = { a.x, a.y, a.z, a.w };
#pragma unroll
        for (int ii = 0; ii < 4; ii++) {
            float2 aa = make_float2(av[ii], av[ii]);
#pragma unroll
            for (int p = 0; p < 8; p++) acc[ii][p] = ffma2(aa, ep[p], acc[ii][p]);
        }
    }

    float4 bi = *(const float4*)(b_ih + i0 + ti);
    float4 bh = *(const float4*)(b_hh + i0 + ti);
    bi.x += bh.x; bi.y += bh.y; bi.z += bh.z; bi.w += bh.w;

#pragma unroll
    for (int p = 0; p < 8; p++) {
        int tb = tb0 + tt + 2 * p;
        if (tb < TBtot) {
            float4 v = make_float4(acc[0][p].x + bi.x, acc[1][p].x + bi.y,
                                   acc[2][p].x + bi.z, acc[3][p].x + bi.w);
            *(float4*)(g_gih + (size_t)tb * Nn + i0 + ti) = v;
        }
        if (tb + 1 < TBtot) {
            float4 v = make_float4(acc[0][p].y + bi.x, acc[1][p].y + bi.y,
                                   acc[2][p].y + bi.z, acc[3][p].y + bi.w);
            *(float4*)(g_gih + (size_t)(tb + 1) * Nn + i0 + ti) = v;
        }
    }
}

// ---------------- RNN step: fp16 W, 2 rows/warp, 256 blocks, double-buffered LDG ----------------
__global__ void k_rnn_step(int t) {
    extern __shared__ float4 hs[];  // 4096 float4 = 64 KB, XOR-swizzled
    const float4* hin = g_h[t & 1];
    float4* hout = g_h[(t + 1) & 1];
    const float* gt = g_gih + (size_t)t * Bz * Nn;

    for (int j = threadIdx.x; j < Nn; j += blockDim.x)
        hs[j ^ ((j >> 3) & 7)] = hin[j];
    __syncthreads();

    int warp = threadIdx.x >> 5, lane = threadIdx.x & 31;
    int gw = blockIdx.x * 8 + warp;        // 0..2047
    int row0 = gw * 2;
    int sw = lane & 7;

    const uint4* w0 = (const uint4*)(g_whh + (size_t)row0 * Nn);        // 512 uint4/row
    const uint4* w1 = (const uint4*)(g_whh + (size_t)(row0 + 1) * Nn);

    uint4 wa = __ldg(w0 + lane);
    uint4 wb = __ldg(w1 + lane);

    float2 a0[4], a1[4];
#pragma unroll
    for (int b = 0; b < 4; b++) { a0[b] = make_float2(0.f, 0.f); a1[b] = make_float2(0.f, 0.f); }

    for (int c = 0; c < 16; c++) {
        uint4 cwa = wa, cwb = wb;
        if (c < 15) {
            int off = (c + 1) * 32 + lane;
            wa = __ldg(w0 + off);
            wb = __ldg(w1 + off);
        }
        int base = c * 256 + lane * 8;     // logical float4 (node) index
        float4 hv[8];
#pragma unroll
        for (int k = 0; k < 8; k++)
            hv[k] = hs[base + (k ^ sw)];   // phys(j) = j ^ ((j>>3)&7); j = base+k

#pragma unroll
        for (int k = 0; k < 8; k += 2) {
            float2 hp0 = make_float2(hv[k].x, hv[k + 1].x);
            float2 hp1 = make_float2(hv[k].y, hv[k + 1].y);
            float2 hp2 = make_float2(hv[k].z, hv[k + 1].z);
            float2 hp3 = make_float2(hv[k].w, hv[k + 1].w);
            float2 wfa = __half22float2(((const __half2*)&cwa)[k >> 1]);
            float2 wfb = __half22float2(((const __half2*)&cwb)[k >> 1]);
            a0[0] = ffma2(wfa, hp0, a0[0]);
            a0[1] = ffma2(wfa, hp1, a0[1]);
            a0[2] = ffma2(wfa, hp2, a0[2]);
            a0[3] = ffma2(wfa, hp3, a0[3]);
            a1[0] = ffma2(wfb, hp0, a1[0]);
            a1[1] = ffma2(wfb, hp1, a1[1]);
            a1[2] = ffma2(wfb, hp2, a1[2]);
            a1[3] = ffma2(wfb, hp3, a1[3]);
        }
    }

    float s0 = a0[0].x + a0[0].y, s1 = a0[1].x + a0[1].y;
    float s2 = a0[2].x + a0[2].y, s3 = a0[3].x + a0[3].y;
    float u0 = a1[0].x + a1[0].y, u1 = a1[1].x + a1[1].y;
    float u2 = a1[2].x + a1[2].y, u3 = a1[3].x + a1[3].y;
#pragma unroll
    for (int o = 16; o; o >>= 1) {
        s0 += __shfl_down_sync(0xffffffffu, s0, o);
        s1 += __shfl_down_sync(0xffffffffu, s1, o);
        s2 += __shfl_down_sync(0xffffffffu, s2, o);
        s3 += __shfl_down_sync(0xffffffffu, s3, o);
        u0 += __shfl_down_sync(0xffffffffu, u0, o);
        u1 += __shfl_down_sync(0xffffffffu, u1, o);
        u2 += __shfl_down_sync(0xffffffffu, u2, o);
        u3 += __shfl_down_sync(0xffffffffu, u3, o);
    }
    if (lane == 0) {
        int i = row0;
        hout[i] = make_float4(tanhf(s0 + gt[0 * Nn + i]), tanhf(s1 + gt[1 * Nn + i]),
                              tanhf(s2 + gt[2 * Nn + i]), tanhf(s3 + gt[3 * Nn + i]));
        int i2 = row0 + 1;
        hout[i2] = make_float4(tanhf(u0 + gt[0 * Nn + i2]), tanhf(u1 + gt[1 * Nn + i2]),
                               tanhf(u2 + gt[2 * Nn + i2]), tanhf(u3 + gt[3 * Nn + i2]));
    }
}

// ---------------- epilogue ----------------
__global__ void k_epi(const float* __restrict__ dW, const float* __restrict__ db,
                      float* __restrict__ out) {
    __shared__ float dWs[Kk * Cout];
    __shared__ float dbs[Kk];
    for (int i = threadIdx.x; i < Kk * Cout; i += blockDim.x) dWs[i] = dW[i];
    if (threadIdx.x < Kk) dbs[threadIdx.x] = db[threadIdx.x];
    __syncthreads();

    int warp = threadIdx.x >> 5, lane = threadIdx.x & 31;
    int gw = blockIdx.x * (blockDim.x >> 5) + warp;  // = b*Nn + n
    if (gw >= Bz * Nn) return;
    int b = gw >> 12;
    int n = gw & (Nn - 1);

    float4 r = ((const float4*)(g_res + (size_t)gw * Cout))[lane];
    float hb = ((const float*)g_h)[(size_t)n * 4 + b];   // g_h[0], [n][b]
    float eh = gelu_exact(hb);

#pragma unroll
    for (int k = 0; k < Kk; k++) {
        const float4* w4 = (const float4*)(dWs + k * Cout);
        float4 w = w4[lane];
        float p = r.x * w.x + r.y * w.y + r.z * w.z + r.w * w.w;
#pragma unroll
        for (int off = 16; off; off >>= 1) p += __shfl_xor_sync(0xffffffffu, p, off);
        if (lane == 0) {
            float s = gelu_exact(p + dbs[k]);
            float v = s * eh;
            out[(size_t)gw * Kk + k] = 1.0f / (1.0f + expf(-v));
        }
    }
}

// ---------------- launch ----------------
extern "C" void kernel_launch(void* const* d_in, const int* in_sizes, int n_in,
                              void* d_out, int out_size) {
    const int*   phi1_idx     = (const int*)d_in[0];
    const float* phi1_val     = (const float*)d_in[1];
    const int*   phi1_inv_idx = (const int*)d_in[2];
    const float* phi1_inv_val = (const float*)d_in[3];
    const int*   phi2_idx     = (const int*)d_in[4];
    const float* phi2_val     = (const float*)d_in[5];
    const int*   phi2_inv_idx = (const int*)d_in[6];
    const float* phi2_inv_val = (const float*)d_in[7];
    const float* fea          = (const float*)d_in[8];
    const int*   joblst       = (const int*)d_in[9];
    const float* W1           = (const float*)d_in[10];
    const float* d1           = (const float*)d_in[11];
    const float* W2           = (const float*)d_in[12];
    const float* d2           = (const float*)d_in[13];
    const float* W_ih         = (const float*)d_in[14];
    const float* W_hh         = (const float*)d_in[15];
    const float* b_ih         = (const float*)d_in[16];
    const float* b_hh         = (const float*)d_in[17];
    const float* dense_W      = (const float*)d_in[18];
    const float* dense_b      = (const float*)d_in[19];
    const float* item_emb     = (const float*)d_in[20];
    float*       out          = (float*)d_out;

    cudaFuncSetAttribute(k_gemm_filt, cudaFuncAttributeMaxDynamicSharedMemorySize, 65536);
    cudaFuncSetAttribute(k_rnn_step, cudaFuncAttributeMaxDynamicSharedMemorySize, 65536);
    cudaFuncSetAttribute(k_gih, cudaFuncAttributeMaxDynamicSharedMemorySize, 2 * 128 * 132 * 4);

    // init scratch + fp16 weight conversion
    k_zero_all<<<2048, 256>>>();
    k_cvt_whh<<<(Nn * Nn / 4) / 256, 256>>>(W_hh);

    // dense inputs
    k_gemm_filt<<<dim3(256, 2), 256, 65536>>>(fea, W1, W2);
    k_gih<<<dim3(32, 2), 256, 2 * 128 * 132 * 4>>>(joblst, item_emb, W_ih, b_ih, b_hh);

    // layer 1
    k_spmm<<<32768, 256>>>(phi1_inv_idx, phi1_inv_val, nullptr, 0, 0);
    k_spmm<<<32768, 256>>>(phi1_idx, phi1_val, d1, 2, 1);

    // layer 2
    k_zero_y<<<2048, 256>>>();
    k_spmm<<<32768, 256>>>(phi2_inv_idx, phi2_inv_val, nullptr, 1, 0);
    k_spmm<<<32768, 256>>>(phi2_idx, phi2_val, d2, 2, 1);

    // RNN: 50 sequential steps
    for (int t = 0; t < Ll; t++) k_rnn_step<<<256, 256, 65536>>>(t);

    // epilogue
    k_epi<<<(Bz * Nn) / 8, 256>>>(dense_W, dense_b, out);
}

// round 5
// speedup vs baseline: 1.7774x; 1.3412x over previous
#include <cuda_runtime.h>
#include <cuda_fp16.h>
#include <math.h>

#define Bz 4
#define Nn 4096
#define Cin 128
#define Cout 128
#define Kk 10
#define Ll 50
#define Ne 65536
#define TBtot (Ll * Bz)   // 200

// ---------------- scratch (static device globals; no allocs) ----------------
__device__ __align__(16) float  g_filt[2 * Bz * Nn * Cout];  // 16 MB
__device__ __align__(16) float  g_y[Bz * Nn * Cout];         // 8 MB
__device__ __align__(16) float  g_res[Bz * Nn * Cout];       // 8 MB
__device__ __align__(16) __half g_h[2][Nn * 4];              // ping-pong hidden: [m][b][j&1] halves
__device__ __align__(16) float  g_gih[TBtot * Nn];           // [t][b][i]
__device__ __align__(16) unsigned char g_w8[Nn * Nn];        // 16 MB fp8 (e4m3, x64-scaled) W_hh

// ---------------- helpers ----------------
__device__ __forceinline__ float gelu_exact(float x) {
    return 0.5f * x * (1.0f + erff(x * 0.7071067811865476f));
}

__device__ __forceinline__ float2 ffma2(float2 a, float2 b, float2 c) {
    unsigned long long au = *reinterpret_cast<unsigned long long*>(&a);
    unsigned long long bu = *reinterpret_cast<unsigned long long*>(&b);
    unsigned long long cu = *reinterpret_cast<unsigned long long*>(&c);
    unsigned long long du;
    asm("fma.rn.f32x2 %0, %1, %2, %3;" : "=l"(du) : "l"(au), "l"(bu), "l"(cu));
    return *reinterpret_cast<float2*>(&du);
}

// pack 2 floats -> e4m3x2 (lo = first arg -> low byte)
__device__ __forceinline__ unsigned short f2e4m3x2(float lo, float hi) {
    unsigned short r;
    asm("cvt.rn.satfinite.e4m3x2.f32 %0, %1, %2;" : "=h"(r) : "f"(hi), "f"(lo));
    return r;
}
// unpack e4m3x2 -> half2 (low byte -> .x)
__device__ __forceinline__ __half2 e4m3x2_2h2(unsigned short v) {
    unsigned int r;
    asm("cvt.rn.f16x2.e4m3x2 %0, %1;" : "=r"(r) : "h"(v));
    return *reinterpret_cast<__half2*>(&r);
}

// ---------------- zero kernels ----------------
__global__ void k_zero_yr() {
    int i = blockIdx.x * blockDim.x + threadIdx.x;   // 524288 threads
    float4 z = make_float4(0.f, 0.f, 0.f, 0.f);
    ((float4*)g_res)[i] = z;
    ((float4*)g_y)[i] = z;
}

__global__ void k_zero_y() {
    int i = blockIdx.x * blockDim.x + threadIdx.x;
    ((float4*)g_y)[i] = make_float4(0.f, 0.f, 0.f, 0.f);
}

// ---------------- W_hh fp32 -> fp8 e4m3 (x64 scale), 16 elems/thread ----------------
__global__ void k_cvt_w8(const float* __restrict__ W) {
    size_t i = (size_t)blockIdx.x * blockDim.x + threadIdx.x;   // Nn*Nn/16 threads
    const float4* w4 = (const float4*)W + i * 4;
    float4 a = __ldg(w4), b = __ldg(w4 + 1), c = __ldg(w4 + 2), d = __ldg(w4 + 3);
    unsigned int r0 = (unsigned int)f2e4m3x2(a.x * 64.f, a.y * 64.f)
                    | ((unsigned int)f2e4m3x2(a.z * 64.f, a.w * 64.f) << 16);
    unsigned int r1 = (unsigned int)f2e4m3x2(b.x * 64.f, b.y * 64.f)
                    | ((unsigned int)f2e4m3x2(b.z * 64.f, b.w * 64.f) << 16);
    unsigned int r2 = (unsigned int)f2e4m3x2(c.x * 64.f, c.y * 64.f)
                    | ((unsigned int)f2e4m3x2(c.z * 64.f, c.w * 64.f) << 16);
    unsigned int r3 = (unsigned int)f2e4m3x2(d.x * 64.f, d.y * 64.f)
                    | ((unsigned int)f2e4m3x2(d.z * 64.f, d.w * 64.f) << 16);
    ((uint4*)g_w8)[i] = make_uint4(r0, r1, r2, r3);
}

// ---------------- filt = fea @ W_l ----------------
__global__ void k_gemm_filt(const float* __restrict__ fea,
                            const float* __restrict__ W1,
                            const float* __restrict__ W2) {
    extern __shared__ float4 Ws[];  // 64 KB
    const float4* W = (const float4*)(blockIdx.y ? W2 : W1);
    for (int i = threadIdx.x; i < Cin * Cout / 4; i += blockDim.x) Ws[i] = W[i];
    __syncthreads();

    int warp = threadIdx.x >> 5, lane = threadIdx.x & 31;
    int nw = blockDim.x >> 5;
    float* out = g_filt + (size_t)blockIdx.y * Bz * Nn * Cout;
    for (int row = blockIdx.x * nw + warp; row < Bz * Nn; row += gridDim.x * nw) {
        const float* fr = fea + (size_t)row * Cin;
        float4 acc = make_float4(0.f, 0.f, 0.f, 0.f);
#pragma unroll 8
        for (int c = 0; c < Cin; c++) {
            float f = __ldg(fr + c);
            float4 w = Ws[c * (Cout / 4) + lane];
            acc.x = fmaf(f, w.x, acc.x);
            acc.y = fmaf(f, w.y, acc.y);
            acc.z = fmaf(f, w.z, acc.z);
            acc.w = fmaf(f, w.w, acc.w);
        }
        ((float4*)(out + (size_t)row * Cout))[lane] = acc;
    }
}

// ---------------- COO spmm (warp per edge, vector atomics) ----------------
__global__ void k_spmm(const int* __restrict__ idx, const float* __restrict__ val,
                       const float* __restrict__ dvec, int xsel, int to_res) {
    int g = blockIdx.x * blockDim.x + threadIdx.x;
    int w = g >> 5, lane = g & 31;
    if (w >= Bz * Ne) return;
    int b = w >> 16;
    int e = w & (Ne - 1);
    const int* ib = idx + (size_t)b * 2 * Ne;
    int r = ib[e];
    int c = ib[Ne + e];
    float v = val[(size_t)b * Ne + e];
    if (dvec) v *= __ldg(dvec + c);
    const float* X = (xsel == 2) ? g_y : (g_filt + (size_t)xsel * Bz * Nn * Cout);
    float* Y = to_res ? g_res : g_y;
    float4 xv = ((const float4*)(X + ((size_t)b * Nn + c) * Cout))[lane];
    float4 add = make_float4(v * xv.x, v * xv.y, v * xv.z, v * xv.w);
    atomicAdd(((float4*)(Y + ((size_t)b * Nn + r) * Cout)) + lane, add);
}

// ---------------- gih: tiled GEMM  C[200,4096] = E[200,128] @ W_ih^T ----------------
// grid (32, 4): 128 i's x 64 tb's per block (128 blocks).
__global__ void k_gih(const int* __restrict__ joblst,
                      const float* __restrict__ item_emb,
                      const float* __restrict__ W_ih,
                      const float* __restrict__ b_ih,
                      const float* __restrict__ b_hh) {
    extern __shared__ float sm[];
    float* As = sm;                   // [128][132]
    float* Es = sm + 128 * 132;       // [128][68]
    int tid = threadIdx.x, lane = tid & 31, warp = tid >> 5;
    int i0 = blockIdx.x * 128, tb0 = blockIdx.y * 64;

#pragma unroll 4
    for (int r = 0; r < 16; r++) {
        int il = warp * 16 + r;
        float4 w = __ldg((const float4*)(W_ih + (size_t)(i0 + il) * Cin) + lane);
        As[(4 * lane + 0) * 132 + il] = w.x;
        As[(4 * lane + 1) * 132 + il] = w.y;
        As[(4 * lane + 2) * 132 + il] = w.z;
        As[(4 * lane + 3) * 132 + il] = w.w;
    }
#pragma unroll 4
    for (int r = 0; r < 8; r++) {
        int tbl = warp * 8 + r;
        int tb = tb0 + tbl;
        int j = 0;
        if (tb < TBtot) { int t = tb >> 2, b = tb & 3; j = joblst[b * Ll + t]; }
        float4 e = __ldg((const float4*)(item_emb + (size_t)j * Cout) + lane);
        Es[(4 * lane + 0) * 68 + tbl] = e.x;
        Es[(4 * lane + 1) * 68 + tbl] = e.y;
        Es[(4 * lane + 2) * 68 + tbl] = e.z;
        Es[(4 * lane + 3) * 68 + tbl] = e.w;
    }
    __syncthreads();

    int ti = lane * 4;       // 4 i's per thread
    int tt = warp * 8;       // 8 tb's per warp
    float2 acc[4][4];
#pragma unroll
    for (int ii = 0; ii < 4; ii++)
#pragma unroll
        for (int p = 0; p < 4; p++) acc[ii][p] = make_float2(0.f, 0.f);

    for (int c = 0; c < 128; c++) {
        float4 a = ((const float4*)(As + c * 132))[lane];
        const float4* er = (const float4*)(Es + c * 68) + (tt >> 2);
        float4 e0 = er[0], e1 = er[1];
        float2 ep[4] = { {e0.x, e0.y}, {e0.z, e0.w}, {e1.x, e1.y}, {e1.z, e1.w} };
        float av[4] = { a.x, a.y, a.z, a.w };
#pragma unroll
        for (int ii = 0; ii < 4; ii++) {
            float2 aa = make_float2(av[ii], av[ii]);
#pragma unroll
            for (int p = 0; p < 4; p++) acc[ii][p] = ffma2(aa, ep[p], acc[ii][p]);
        }
    }

    float4 bi = *(const float4*)(b_ih + i0 + ti);
    float4 bh = *(const float4*)(b_hh + i0 + ti);
    bi.x += bh.x; bi.y += bh.y; bi.z += bh.z; bi.w += bh.w;

#pragma unroll
    for (int p = 0; p < 4; p++) {
        int tb = tb0 + tt + 2 * p;
        if (tb < TBtot) {
            float4 v = make_float4(acc[0][p].x + bi.x, acc[1][p].x + bi.y,
                                   acc[2][p].x + bi.z, acc[3][p].x + bi.w);
            *(float4*)(g_gih + (size_t)tb * Nn + i0 + ti) = v;
        }
        if (tb + 1 < TBtot) {
            float4 v = make_float4(acc[0][p].y + bi.x, acc[1][p].y + bi.y,
                                   acc[2][p].y + bi.z, acc[3][p].y + bi.w);
            *(float4*)(g_gih + (size_t)(tb + 1) * Nn + i0 + ti) = v;
        }
    }
}

// ---------------- RNN step: fp8 W (x64), fp16 h, HFMA2, 2 rows/warp ----------------
// grid 256 x 256 thr (8 warps); warp gw handles rows 2gw, 2gw+1.
// h layout: per node-pair m: uint4 = { half2(b0: h_2m,h_2m+1), b1, b2, b3 }
__global__ void k_rnn_step(int t) {
    __shared__ uint4 hs[Nn / 2];   // 32 KB, XOR-swizzled
    const float* gt = g_gih + (size_t)t * Bz * Nn;
    int warp = threadIdx.x >> 5, lane = threadIdx.x & 31;
    int gw = blockIdx.x * 8 + warp;        // 0..2047
    int row0 = gw * 2;

    float2 facc[2][4];                      // [row][batch], f32 chunk accumulators
#pragma unroll
    for (int r = 0; r < 2; r++)
#pragma unroll
        for (int b = 0; b < 4; b++) facc[r][b] = make_float2(0.f, 0.f);

    if (t > 0) {
        const uint4* hin = (const uint4*)g_h[t & 1];
        for (int m = threadIdx.x; m < Nn / 2; m += 256)
            hs[m ^ ((m >> 3) & 7)] = hin[m];
        __syncthreads();

        const uint4* w0 = (const uint4*)(g_w8 + (size_t)row0 * Nn);   // 256 uint4/row
        const uint4* w1 = w0 + 256;
        int sw = lane & 7;

        uint4 wbuf[2][2];
        wbuf[0][0] = __ldg(w0 + lane);        wbuf[0][1] = __ldg(w1 + lane);
        wbuf[1][0] = __ldg(w0 + 32 + lane);   wbuf[1][1] = __ldg(w1 + 32 + lane);

        for (int c = 0; c < 8; c++) {
            uint4 wa = wbuf[c & 1][0], wb = wbuf[c & 1][1];
            if (c < 6) {
                wbuf[c & 1][0] = __ldg(w0 + (c + 2) * 32 + lane);
                wbuf[c & 1][1] = __ldg(w1 + (c + 2) * 32 + lane);
            }
            int base = c * 256 + lane * 8;
            uint4 hv[8];
#pragma unroll
            for (int k = 0; k < 8; k++)
                hv[k] = hs[base + (k ^ sw)];   // logical m = base + k

            __half2 acc[2][4];
#pragma unroll
            for (int r = 0; r < 2; r++)
#pragma unroll
                for (int b = 0; b < 4; b++) acc[r][b] = __floats2half2_rn(0.f, 0.f);

            const unsigned int* wa32 = (const unsigned int*)&wa;
            const unsigned int* wb32 = (const unsigned int*)&wb;
#pragma unroll
            for (int k = 0; k < 8; k++) {
                unsigned short ua = (unsigned short)(wa32[k >> 1] >> (16 * (k & 1)));
                unsigned short ub = (unsigned short)(wb32[k >> 1] >> (16 * (k & 1)));
                __half2 wha = e4m3x2_2h2(ua);
                __half2 whb = e4m3x2_2h2(ub);
                const __half2* hp = (const __half2*)&hv[k];
#pragma unroll
                for (int b = 0; b < 4; b++) {
                    acc[0][b] = __hfma2(wha, hp[b], acc[0][b]);
                    acc[1][b] = __hfma2(whb, hp[b], acc[1][b]);
                }
            }
#pragma unroll
            for (int r = 0; r < 2; r++)
#pragma unroll
                for (int b = 0; b < 4; b++) {
                    float2 f = __half22float2(acc[r][b]);
                    facc[r][b].x += f.x;
                    facc[r][b].y += f.y;
                }
        }
    }

    // reduce across lanes
    float s[2][4];
#pragma unroll
    for (int r = 0; r < 2; r++)
#pragma unroll
        for (int b = 0; b < 4; b++) {
            float v = (facc[r][b].x + facc[r][b].y) * 0.015625f;   // /64 scale
#pragma unroll
            for (int o = 16; o; o >>= 1) v += __shfl_down_sync(0xffffffffu, v, o);
            s[r][b] = v;
        }

    if (lane == 0) {
        uint4* hout = (uint4*)g_h[(t + 1) & 1];
        float h0[4], h1[4];
#pragma unroll
        for (int b = 0; b < 4; b++) {
            h0[b] = tanhf(s[0][b] + gt[b * Nn + row0]);
            h1[b] = tanhf(s[1][b] + gt[b * Nn + row0 + 1]);
        }
        __half2 o0 = __floats2half2_rn(h0[0], h1[0]);
        __half2 o1 = __floats2half2_rn(h0[1], h1[1]);
        __half2 o2 = __floats2half2_rn(h0[2], h1[2]);
        __half2 o3 = __floats2half2_rn(h0[3], h1[3]);
        hout[gw] = make_uint4(*(unsigned int*)&o0, *(unsigned int*)&o1,
                              *(unsigned int*)&o2, *(unsigned int*)&o3);
    }
}

// ---------------- epilogue ----------------
__global__ void k_epi(const float* __restrict__ dW, const float* __restrict__ db,
                      float* __restrict__ out) {
    __shared__ float dWs[Kk * Cout];
    __shared__ float dbs[Kk];
    for (int i = threadIdx.x; i < Kk * Cout; i += blockDim.x) dWs[i] = dW[i];
    if (threadIdx.x < Kk) dbs[threadIdx.x] = db[threadIdx.x];
    __syncthreads();

    int warp = threadIdx.x >> 5, lane = threadIdx.x & 31;
    int gw = blockIdx.x * (blockDim.x >> 5) + warp;  // = b*Nn + n
    if (gw >= Bz * Nn) return;
    int b = gw >> 12;
    int n = gw & (Nn - 1);

    float4 r = ((const float4*)(g_res + (size_t)gw * Cout))[lane];
    // final hidden in g_h[0]: halves [m][b][n&1]
    float hb = __half2float(g_h[0][(size_t)(n >> 1) * 8 + b * 2 + (n & 1)]);
    float eh = gelu_exact(hb);

#pragma unroll
    for (int k = 0; k < Kk; k++) {
        const float4* w4 = (const float4*)(dWs + k * Cout);
        float4 w = w4[lane];
        float p = r.x * w.x + r.y * w.y + r.z * w.z + r.w * w.w;
#pragma unroll
        for (int off = 16; off; off >>= 1) p += __shfl_xor_sync(0xffffffffu, p, off);
        if (lane == 0) {
            float s = gelu_exact(p + dbs[k]);
            float v = s * eh;
            out[(size_t)gw * Kk + k] = 1.0f / (1.0f + expf(-v));
        }
    }
}

// ---------------- launch ----------------
extern "C" void kernel_launch(void* const* d_in, const int* in_sizes, int n_in,
                              void* d_out, int out_size) {
    const int*   phi1_idx     = (const int*)d_in[0];
    const float* phi1_val     = (const float*)d_in[1];
    const int*   phi1_inv_idx = (const int*)d_in[2];
    const float* phi1_inv_val = (const float*)d_in[3];
    const int*   phi2_idx     = (const int*)d_in[4];
    const float* phi2_val     = (const float*)d_in[5];
    const int*   phi2_inv_idx = (const int*)d_in[6];
    const float* phi2_inv_val = (const float*)d_in[7];
    const float* fea          = (const float*)d_in[8];
    const int*   joblst       = (const int*)d_in[9];
    const float* W1           = (const float*)d_in[10];
    const float* d1           = (const float*)d_in[11];
    const float* W2           = (const float*)d_in[12];
    const float* d2           = (const float*)d_in[13];
    const float* W_ih         = (const float*)d_in[14];
    const float* W_hh         = (const float*)d_in[15];
    const float* b_ih         = (const float*)d_in[16];
    const float* b_hh         = (const float*)d_in[17];
    const float* dense_W      = (const float*)d_in[18];
    const float* dense_b      = (const float*)d_in[19];
    const float* item_emb     = (const float*)d_in[20];
    float*       out          = (float*)d_out;

    static cudaStream_t s2 = nullptr;
    static cudaEvent_t ev0 = nullptr, ev1 = nullptr;
    if (!s2) {
        cudaStreamCreateWithFlags(&s2, cudaStreamNonBlocking);
        cudaEventCreateWithFlags(&ev0, cudaEventDisableTiming);
        cudaEventCreateWithFlags(&ev1, cudaEventDisableTiming);
        cudaFuncSetAttribute(k_gemm_filt, cudaFuncAttributeMaxDynamicSharedMemorySize, 65536);
        cudaFuncSetAttribute(k_gih, cudaFuncAttributeMaxDynamicSharedMemorySize,
                             (128 * 132 + 128 * 68) * 4);
    }

    // fork: conv chain on s2
    cudaEventRecord(ev0, 0);
    cudaStreamWaitEvent(s2, ev0, 0);

    // ---- chain B (s2): conv path -> g_res ----
    k_zero_yr<<<2048, 256, 0, s2>>>();
    k_gemm_filt<<<dim3(256, 2), 256, 65536, s2>>>(fea, W1, W2);
    k_spmm<<<32768, 256, 0, s2>>>(phi1_inv_idx, phi1_inv_val, nullptr, 0, 0);
    k_spmm<<<32768, 256, 0, s2>>>(phi1_idx, phi1_val, d1, 2, 1);
    k_zero_y<<<2048, 256, 0, s2>>>();
    k_spmm<<<32768, 256, 0, s2>>>(phi2_inv_idx, phi2_inv_val, nullptr, 1, 0);
    k_spmm<<<32768, 256, 0, s2>>>(phi2_idx, phi2_val, d2, 2, 1);
    cudaEventRecord(ev1, s2);

    // ---- chain A (default stream): RNN path -> g_h[0] ----
    k_cvt_w8<<<4096, 256>>>(W_hh);
    k_gih<<<dim3(32, 4), 256, (128 * 132 + 128 * 68) * 4>>>(joblst, item_emb, W_ih, b_ih, b_hh);
    for (int t = 0; t < Ll; t++) k_rnn_step<<<256, 256>>>(t);

    // join + epilogue
    cudaStreamWaitEvent(0, ev1, 0);
    k_epi<<<(Bz * Nn) / 8, 256>>>(dense_W, dense_b, out);
}

// round 6
// speedup vs baseline: 2.4128x; 1.3575x over previous
#include <cuda_runtime.h>
#include <cuda_fp16.h>
#include <math.h>

#define Bz 4
#define Nn 4096
#define Cin 128
#define Cout 128
#define Kk 10
#define Ll 50
#define Ne 65536
#define TBtot (Ll * Bz)   // 200
#define RNN_BLOCKS 128

// ---------------- scratch (static device globals; no allocs) ----------------
__device__ __align__(16) float  g_filt[2 * Bz * Nn * Cout];  // 16 MB
__device__ __align__(16) float  g_y[Bz * Nn * Cout];         // 8 MB
__device__ __align__(16) float  g_res[Bz * Nn * Cout];       // 8 MB
__device__ __align__(16) __half g_h[2][Nn * 4];              // ping-pong hidden: [m][b][j&1]
__device__ __align__(16) float  g_gih[TBtot * Nn];           // [t][b][i]
__device__ __align__(16) unsigned char g_w8[Nn * Nn];        // 16 MB fp8 (e4m3, x64) W_hh
__device__ unsigned int g_bar;                               // grid barrier counter

// ---------------- helpers ----------------
__device__ __forceinline__ float gelu_exact(float x) {
    return 0.5f * x * (1.0f + erff(x * 0.7071067811865476f));
}

__device__ __forceinline__ float2 ffma2(float2 a, float2 b, float2 c) {
    unsigned long long au = *reinterpret_cast<unsigned long long*>(&a);
    unsigned long long bu = *reinterpret_cast<unsigned long long*>(&b);
    unsigned long long cu = *reinterpret_cast<unsigned long long*>(&c);
    unsigned long long du;
    asm("fma.rn.f32x2 %0, %1, %2, %3;" : "=l"(du) : "l"(au), "l"(bu), "l"(cu));
    return *reinterpret_cast<float2*>(&du);
}

__device__ __forceinline__ unsigned short f2e4m3x2(float lo, float hi) {
    unsigned short r;
    asm("cvt.rn.satfinite.e4m3x2.f32 %0, %1, %2;" : "=h"(r) : "f"(hi), "f"(lo));
    return r;
}
__device__ __forceinline__ __half2 e4m3x2_2h2(unsigned short v) {
    unsigned int r;
    asm("cvt.rn.f16x2.e4m3x2 %0, %1;" : "=r"(r) : "h"(v));
    return *reinterpret_cast<__half2*>(&r);
}

__device__ __forceinline__ uint4 ldcg_u4(const uint4* p) {
    uint4 v;
    asm volatile("ld.global.cg.v4.u32 {%0,%1,%2,%3}, [%4];"
                 : "=r"(v.x), "=r"(v.y), "=r"(v.z), "=r"(v.w) : "l"(p));
    return v;
}

// ---------------- zero kernels ----------------
__global__ void k_zero_yr() {
    int i = blockIdx.x * blockDim.x + threadIdx.x;
    float4 z = make_float4(0.f, 0.f, 0.f, 0.f);
    ((float4*)g_res)[i] = z;
    ((float4*)g_y)[i] = z;
}

__global__ void k_zero_y() {
    int i = blockIdx.x * blockDim.x + threadIdx.x;
    ((float4*)g_y)[i] = make_float4(0.f, 0.f, 0.f, 0.f);
}

// ---------------- W_hh fp32 -> fp8 e4m3 (x64 scale); also resets barrier ----------------
__global__ void k_cvt_w8(const float* __restrict__ W) {
    if (blockIdx.x == 0 && threadIdx.x == 0) g_bar = 0u;
    size_t i = (size_t)blockIdx.x * blockDim.x + threadIdx.x;   // Nn*Nn/16 threads
    const float4* w4 = (const float4*)W + i * 4;
    float4 a = __ldg(w4), b = __ldg(w4 + 1), c = __ldg(w4 + 2), d = __ldg(w4 + 3);
    unsigned int r0 = (unsigned int)f2e4m3x2(a.x * 64.f, a.y * 64.f)
                    | ((unsigned int)f2e4m3x2(a.z * 64.f, a.w * 64.f) << 16);
    unsigned int r1 = (unsigned int)f2e4m3x2(b.x * 64.f, b.y * 64.f)
                    | ((unsigned int)f2e4m3x2(b.z * 64.f, b.w * 64.f) << 16);
    unsigned int r2 = (unsigned int)f2e4m3x2(c.x * 64.f, c.y * 64.f)
                    | ((unsigned int)f2e4m3x2(c.z * 64.f, c.w * 64.f) << 16);
    unsigned int r3 = (unsigned int)f2e4m3x2(d.x * 64.f, d.y * 64.f)
                    | ((unsigned int)f2e4m3x2(d.z * 64.f, d.w * 64.f) << 16);
    ((uint4*)g_w8)[i] = make_uint4(r0, r1, r2, r3);
}

// ---------------- filt = fea @ W_l ----------------
__global__ void k_gemm_filt(const float* __restrict__ fea,
                            const float* __restrict__ W1,
                            const float* __restrict__ W2) {
    extern __shared__ float4 Ws[];  // 64 KB
    const float4* W = (const float4*)(blockIdx.y ? W2 : W1);
    for (int i = threadIdx.x; i < Cin * Cout / 4; i += blockDim.x) Ws[i] = W[i];
    __syncthreads();

    int warp = threadIdx.x >> 5, lane = threadIdx.x & 31;
    int nw = blockDim.x >> 5;
    float* out = g_filt + (size_t)blockIdx.y * Bz * Nn * Cout;
    for (int row = blockIdx.x * nw + warp; row < Bz * Nn; row += gridDim.x * nw) {
        const float* fr = fea + (size_t)row * Cin;
        float4 acc = make_float4(0.f, 0.f, 0.f, 0.f);
#pragma unroll 8
        for (int c = 0; c < Cin; c++) {
            float f = __ldg(fr + c);
            float4 w = Ws[c * (Cout / 4) + lane];
            acc.x = fmaf(f, w.x, acc.x);
            acc.y = fmaf(f, w.y, acc.y);
            acc.z = fmaf(f, w.z, acc.z);
            acc.w = fmaf(f, w.w, acc.w);
        }
        ((float4*)(out + (size_t)row * Cout))[lane] = acc;
    }
}

// ---------------- COO spmm (warp per edge, vector atomics) ----------------
__global__ void k_spmm(const int* __restrict__ idx, const float* __restrict__ val,
                       const float* __restrict__ dvec, int xsel, int to_res) {
    int g = blockIdx.x * blockDim.x + threadIdx.x;
    int w = g >> 5, lane = g & 31;
    if (w >= Bz * Ne) return;
    int b = w >> 16;
    int e = w & (Ne - 1);
    const int* ib = idx + (size_t)b * 2 * Ne;
    int r = ib[e];
    int c = ib[Ne + e];
    float v = val[(size_t)b * Ne + e];
    if (dvec) v *= __ldg(dvec + c);
    const float* X = (xsel == 2) ? g_y : (g_filt + (size_t)xsel * Bz * Nn * Cout);
    float* Y = to_res ? g_res : g_y;
    float4 xv = ((const float4*)(X + ((size_t)b * Nn + c) * Cout))[lane];
    float4 add = make_float4(v * xv.x, v * xv.y, v * xv.z, v * xv.w);
    atomicAdd(((float4*)(Y + ((size_t)b * Nn + r) * Cout)) + lane, add);
}

// ---------------- gih: tiled GEMM  C[200,4096] = E[200,128] @ W_ih^T ----------------
__global__ void k_gih(const int* __restrict__ joblst,
                      const float* __restrict__ item_emb,
                      const float* __restrict__ W_ih,
                      const float* __restrict__ b_ih,
                      const float* __restrict__ b_hh) {
    extern __shared__ float sm[];
    float* As = sm;                   // [128][132]
    float* Es = sm + 128 * 132;       // [128][68]
    int tid = threadIdx.x, lane = tid & 31, warp = tid >> 5;
    int i0 = blockIdx.x * 128, tb0 = blockIdx.y * 64;

#pragma unroll 4
    for (int r = 0; r < 16; r++) {
        int il = warp * 16 + r;
        float4 w = __ldg((const float4*)(W_ih + (size_t)(i0 + il) * Cin) + lane);
        As[(4 * lane + 0) * 132 + il] = w.x;
        As[(4 * lane + 1) * 132 + il] = w.y;
        As[(4 * lane + 2) * 132 + il] = w.z;
        As[(4 * lane + 3) * 132 + il] = w.w;
    }
#pragma unroll 4
    for (int r = 0; r < 8; r++) {
        int tbl = warp * 8 + r;
        int tb = tb0 + tbl;
        int j = 0;
        if (tb < TBtot) { int t = tb >> 2, b = tb & 3; j = joblst[b * Ll + t]; }
        float4 e = __ldg((const float4*)(item_emb + (size_t)j * Cout) + lane);
        Es[(4 * lane + 0) * 68 + tbl] = e.x;
        Es[(4 * lane + 1) * 68 + tbl] = e.y;
        Es[(4 * lane + 2) * 68 + tbl] = e.z;
        Es[(4 * lane + 3) * 68 + tbl] = e.w;
    }
    __syncthreads();

    int ti = lane * 4;
    int tt = warp * 8;
    float2 acc[4][4];
#pragma unroll
    for (int ii = 0; ii < 4; ii++)
#pragma unroll
        for (int p = 0; p < 4; p++) acc[ii][p] = make_float2(0.f, 0.f);

    for (int c = 0; c < 128; c++) {
        float4 a = ((const float4*)(As + c * 132))[lane];
        const float4* er = (const float4*)(Es + c * 68) + (tt >> 2);
        float4 e0 = er[0], e1 = er[1];
        float2 ep[4] = { {e0.x, e0.y}, {e0.z, e0.w}, {e1.x, e1.y}, {e1.z, e1.w} };
        float av[4] = { a.x, a.y, a.z, a.w };
#pragma unroll
        for (int ii = 0; ii < 4; ii++) {
            float2 aa = make_float2(av[ii], av[ii]);
#pragma unroll
            for (int p = 0; p < 4; p++) acc[ii][p] = ffma2(aa, ep[p], acc[ii][p]);
        }
    }

    float4 bi = *(const float4*)(b_ih + i0 + ti);
    float4 bh = *(const float4*)(b_hh + i0 + ti);
    bi.x += bh.x; bi.y += bh.y; bi.z += bh.z; bi.w += bh.w;

#pragma unroll
    for (int p = 0; p < 4; p++) {
        int tb = tb0 + tt + 2 * p;
        if (tb < TBtot) {
            float4 v = make_float4(acc[0][p].x + bi.x, acc[1][p].x + bi.y,
                                   acc[2][p].x + bi.z, acc[3][p].x + bi.w);
            *(float4*)(g_gih + (size_t)tb * Nn + i0 + ti) = v;
        }
        if (tb + 1 < TBtot) {
            float4 v = make_float4(acc[0][p].y + bi.x, acc[1][p].y + bi.y,
                                   acc[2][p].y + bi.z, acc[3][p].y + bi.w);
            *(float4*)(g_gih + (size_t)(tb + 1) * Nn + i0 + ti) = v;
        }
    }
}

// ---------------- persistent RNN: all 50 steps, W in registers ----------------
// 128 blocks x 256 thr (8 warps); warp gw owns rows 4gw..4gw+3.
// h layout per node-pair m: uint4 = { half2(b0: h_2m, h_2m+1), b1, b2, b3 }
__global__ void __launch_bounds__(256, 1) k_rnn_all() {
    __shared__ uint4 hs[Nn / 2];   // 32 KB, XOR-swizzled
    int warp = threadIdx.x >> 5, lane = threadIdx.x & 31;
    int gw = blockIdx.x * 8 + warp;        // 0..1023
    int row0 = gw * 4;
    int sw = lane & 7;

    // load W slice into registers once: wreg[r][c] covers row row0+r, j-chunk c
    uint4 wreg[4][8];
#pragma unroll
    for (int r = 0; r < 4; r++) {
        const uint4* wp = (const uint4*)(g_w8 + (size_t)(row0 + r) * Nn);
#pragma unroll
        for (int c = 0; c < 8; c++) wreg[r][c] = __ldg(wp + c * 32 + lane);
    }

    for (int t = 0; t < Ll; t++) {
        if (t > 0) {
            const uint4* hin = (const uint4*)g_h[t & 1];
            for (int m = threadIdx.x; m < Nn / 2; m += 256)
                hs[m ^ ((m >> 3) & 7)] = ldcg_u4(hin + m);   // .cg: ping-pong reuse, skip L1
        }
        __syncthreads();

        float2 facc[4][4];
#pragma unroll
        for (int r = 0; r < 4; r++)
#pragma unroll
            for (int b = 0; b < 4; b++) facc[r][b] = make_float2(0.f, 0.f);

        if (t > 0) {
#pragma unroll
            for (int c = 0; c < 8; c++) {
                int base = c * 256 + lane * 8;
                uint4 hv[8];
#pragma unroll
                for (int k = 0; k < 8; k++)
                    hv[k] = hs[base + (k ^ sw)];   // logical m = base + k

                __half2 hacc[4][4];
#pragma unroll
                for (int r = 0; r < 4; r++)
#pragma unroll
                    for (int b = 0; b < 4; b++) hacc[r][b] = __floats2half2_rn(0.f, 0.f);

#pragma unroll
                for (int k = 0; k < 8; k++) {
                    const __half2* hp = (const __half2*)&hv[k];
#pragma unroll
                    for (int r = 0; r < 4; r++) {
                        unsigned int w32 = ((const unsigned int*)&wreg[r][c])[k >> 1];
                        unsigned short u = (unsigned short)(w32 >> (16 * (k & 1)));
                        __half2 wh = e4m3x2_2h2(u);
#pragma unroll
                        for (int b = 0; b < 4; b++)
                            hacc[r][b] = __hfma2(wh, hp[b], hacc[r][b]);
                    }
                }
#pragma unroll
                for (int r = 0; r < 4; r++)
#pragma unroll
                    for (int b = 0; b < 4; b++) {
                        float2 f = __half22float2(hacc[r][b]);
                        facc[r][b].x += f.x;
                        facc[r][b].y += f.y;
                    }
            }
        }

        // lane reduction
        float s[4][4];
#pragma unroll
        for (int r = 0; r < 4; r++)
#pragma unroll
            for (int b = 0; b < 4; b++) {
                float v = (facc[r][b].x + facc[r][b].y) * 0.015625f;   // /64
#pragma unroll
                for (int o = 16; o; o >>= 1) v += __shfl_down_sync(0xffffffffu, v, o);
                s[r][b] = v;
            }

        if (lane == 0) {
            const float* gt = g_gih + (size_t)t * Bz * Nn;
            uint4* hout = (uint4*)g_h[(t + 1) & 1];
            float hv[4][4];
#pragma unroll
            for (int r = 0; r < 4; r++)
#pragma unroll
                for (int b = 0; b < 4; b++)
                    hv[r][b] = tanhf(s[r][b] + gt[b * Nn + row0 + r]);
            __half2 p0 = __floats2half2_rn(hv[0][0], hv[1][0]);
            __half2 p1 = __floats2half2_rn(hv[0][1], hv[1][1]);
            __half2 p2 = __floats2half2_rn(hv[0][2], hv[1][2]);
            __half2 p3 = __floats2half2_rn(hv[0][3], hv[1][3]);
            hout[2 * gw] = make_uint4(*(unsigned int*)&p0, *(unsigned int*)&p1,
                                      *(unsigned int*)&p2, *(unsigned int*)&p3);
            __half2 q0 = __floats2half2_rn(hv[2][0], hv[3][0]);
            __half2 q1 = __floats2half2_rn(hv[2][1], hv[3][1]);
            __half2 q2 = __floats2half2_rn(hv[2][2], hv[3][2]);
            __half2 q3 = __floats2half2_rn(hv[2][3], hv[3][3]);
            hout[2 * gw + 1] = make_uint4(*(unsigned int*)&q0, *(unsigned int*)&q1,
                                          *(unsigned int*)&q2, *(unsigned int*)&q3);
        }

        // grid barrier
        __syncthreads();
        if (threadIdx.x == 0) {
            __threadfence();
            atomicAdd(&g_bar, 1u);
            unsigned int target = (unsigned int)RNN_BLOCKS * (t + 1);
            while (atomicAdd(&g_bar, 0u) < target) __nanosleep(32);
        }
        __syncthreads();
    }
}

// ---------------- epilogue ----------------
__global__ void k_epi(const float* __restrict__ dW, const float* __restrict__ db,
                      float* __restrict__ out) {
    __shared__ float dWs[Kk * Cout];
    __shared__ float dbs[Kk];
    for (int i = threadIdx.x; i < Kk * Cout; i += blockDim.x) dWs[i] = dW[i];
    if (threadIdx.x < Kk) dbs[threadIdx.x] = db[threadIdx.x];
    __syncthreads();

    int warp = threadIdx.x >> 5, lane = threadIdx.x & 31;
    int gw = blockIdx.x * (blockDim.x >> 5) + warp;  // = b*Nn + n
    if (gw >= Bz * Nn) return;
    int b = gw >> 12;
    int n = gw & (Nn - 1);

    float4 r = ((const float4*)(g_res + (size_t)gw * Cout))[lane];
    float hb = __half2float(g_h[0][(size_t)(n >> 1) * 8 + b * 2 + (n & 1)]);
    float eh = gelu_exact(hb);

#pragma unroll
    for (int k = 0; k < Kk; k++) {
        const float4* w4 = (const float4*)(dWs + k * Cout);
        float4 w = w4[lane];
        float p = r.x * w.x + r.y * w.y + r.z * w.z + r.w * w.w;
#pragma unroll
        for (int off = 16; off; off >>= 1) p += __shfl_xor_sync(0xffffffffu, p, off);
        if (lane == 0) {
            float s = gelu_exact(p + dbs[k]);
            float v = s * eh;
            out[(size_t)gw * Kk + k] = 1.0f / (1.0f + expf(-v));
        }
    }
}

// ---------------- launch ----------------
extern "C" void kernel_launch(void* const* d_in, const int* in_sizes, int n_in,
                              void* d_out, int out_size) {
    const int*   phi1_idx     = (const int*)d_in[0];
    const float* phi1_val     = (const float*)d_in[1];
    const int*   phi1_inv_idx = (const int*)d_in[2];
    const float* phi1_inv_val = (const float*)d_in[3];
    const int*   phi2_idx     = (const int*)d_in[4];
    const float* phi2_val     = (const float*)d_in[5];
    const int*   phi2_inv_idx = (const int*)d_in[6];
    const float* phi2_inv_val = (const float*)d_in[7];
    const float* fea          = (const float*)d_in[8];
    const int*   joblst       = (const int*)d_in[9];
    const float* W1           = (const float*)d_in[10];
    const float* d1           = (const float*)d_in[11];
    const float* W2           = (const float*)d_in[12];
    const float* d2           = (const float*)d_in[13];
    const float* W_ih         = (const float*)d_in[14];
    const float* W_hh         = (const float*)d_in[15];
    const float* b_ih         = (const float*)d_in[16];
    const float* b_hh         = (const float*)d_in[17];
    const float* dense_W      = (const float*)d_in[18];
    const float* dense_b      = (const float*)d_in[19];
    const float* item_emb     = (const float*)d_in[20];
    float*       out          = (float*)d_out;

    static cudaStream_t s2 = nullptr;
    static cudaEvent_t ev0 = nullptr, ev1 = nullptr;
    if (!s2) {
        cudaStreamCreateWithFlags(&s2, cudaStreamNonBlocking);
        cudaEventCreateWithFlags(&ev0, cudaEventDisableTiming);
        cudaEventCreateWithFlags(&ev1, cudaEventDisableTiming);
        cudaFuncSetAttribute(k_gemm_filt, cudaFuncAttributeMaxDynamicSharedMemorySize, 65536);
        cudaFuncSetAttribute(k_gih, cudaFuncAttributeMaxDynamicSharedMemorySize,
                             (128 * 132 + 128 * 68) * 4);
    }

    // fork: conv chain on s2
    cudaEventRecord(ev0, 0);
    cudaStreamWaitEvent(s2, ev0, 0);

    // ---- chain B (s2): conv path -> g_res ----
    k_zero_yr<<<2048, 256, 0, s2>>>();
    k_gemm_filt<<<dim3(256, 2), 256, 65536, s2>>>(fea, W1, W2);
    k_spmm<<<32768, 256, 0, s2>>>(phi1_inv_idx, phi1_inv_val, nullptr, 0, 0);
    k_spmm<<<32768, 256, 0, s2>>>(phi1_idx, phi1_val, d1, 2, 1);
    k_zero_y<<<2048, 256, 0, s2>>>();
    k_spmm<<<32768, 256, 0, s2>>>(phi2_inv_idx, phi2_inv_val, nullptr, 1, 0);
    k_spmm<<<32768, 256, 0, s2>>>(phi2_idx, phi2_val, d2, 2, 1);
    cudaEventRecord(ev1, s2);

    // ---- chain A (default stream): RNN path -> g_h[0] ----
    k_cvt_w8<<<4096, 256>>>(W_hh);    // also resets g_bar
    k_gih<<<dim3(32, 4), 256, (128 * 132 + 128 * 68) * 4>>>(joblst, item_emb, W_ih, b_ih, b_hh);
    k_rnn_all<<<RNN_BLOCKS, 256>>>();

    // join + epilogue
    cudaStreamWaitEvent(0, ev1, 0);
    k_epi<<<(Bz * Nn) / 8, 256>>>(dense_W, dense_b, out);
}